// round 4
// baseline (speedup 1.0000x reference)
#include <cuda_runtime.h>
#include <math_constants.h>

// Problem dimensions (fixed by the reference)
#define Bd  4
#define Sd  2048
#define Dd  1024
#define Hn  16
#define DHd 64
#define Fd  4096

// ---------------------------------------------------------------------------
// Scratch (device globals — allocation-free rule)
// ---------------------------------------------------------------------------
__device__ float g_q  [(size_t)Bd * Hn * Sd * DHd];   // [B,H,S,DH]
__device__ float g_k  [(size_t)Bd * Hn * Sd * DHd];
__device__ float g_v  [(size_t)Bd * Hn * Sd * DHd];
__device__ float g_o  [(size_t)Bd * Sd * Dd];         // attention concat [B*S, D]
__device__ float g_r1 [(size_t)Bd * Sd * Dd];         // x + attn_proj
__device__ float g_y  [(size_t)Bd * Sd * Dd];         // LN1 output
__device__ float g_hid[(size_t)Bd * Sd * Fd];         // FFN hidden [B*S, F]
__device__ float g_r2 [(size_t)Bd * Sd * Dd];         // y + ffn

// ---------------------------------------------------------------------------
// Generic 128x128 SGEMM, BK=16, 256 threads, 8x8 micro-tile.
// C[M,N] = A[M,K](row,lda) @ B[K,N](row,ldb) + bias[N]  (+res / relu per MODE)
// MODE: 0 = bias; 1 = bias + residual; 2 = bias + relu
// ---------------------------------------------------------------------------
template<int MODE>
__global__ __launch_bounds__(256, 2)
void sgemm128(const float* __restrict__ A, int lda,
              const float* __restrict__ B, int ldb,
              float* __restrict__ C,
              const float* __restrict__ bias,
              const float* __restrict__ res,
              int N, int K)
{
    __shared__ float As[16][132];   // transposed A tile, padded (132*4B = 16B-aligned rows)
    __shared__ float Bs[16][128];

    const int tid = threadIdx.x;
    const int tx = tid & 15;
    const int ty = tid >> 4;
    const long m0 = (long)blockIdx.y * 128;
    const long n0 = (long)blockIdx.x * 128;

    const int ar = tid >> 2;          // 0..63
    const int ac = (tid & 3) << 2;    // 0,4,8,12
    const int br = tid >> 4;          // 0..15
    const int bc = (tid & 15) << 2;   // 0..60

    const float* Ap  = A + (m0 + ar)      * (long)lda;
    const float* Ap2 = A + (m0 + ar + 64) * (long)lda;
    const float* Bp  = B + (long)br * ldb + n0;

    float acc[8][8];
    #pragma unroll
    for (int i = 0; i < 8; i++)
        #pragma unroll
        for (int j = 0; j < 8; j++) acc[i][j] = 0.f;

    for (int k0 = 0; k0 < K; k0 += 16) {
        float4 a0 = *(const float4*)(Ap  + k0 + ac);
        float4 a1 = *(const float4*)(Ap2 + k0 + ac);
        float4 b0 = *(const float4*)(Bp + (long)k0 * ldb + bc);
        float4 b1 = *(const float4*)(Bp + (long)k0 * ldb + bc + 64);
        __syncthreads();
        As[ac+0][ar]    = a0.x; As[ac+1][ar]    = a0.y;
        As[ac+2][ar]    = a0.z; As[ac+3][ar]    = a0.w;
        As[ac+0][ar+64] = a1.x; As[ac+1][ar+64] = a1.y;
        As[ac+2][ar+64] = a1.z; As[ac+3][ar+64] = a1.w;
        *(float4*)&Bs[br][bc]      = b0;
        *(float4*)&Bs[br][bc + 64] = b1;
        __syncthreads();
        #pragma unroll
        for (int kk = 0; kk < 16; kk++) {
            float4 xa0 = *(const float4*)&As[kk][ty * 4];
            float4 xa1 = *(const float4*)&As[kk][64 + ty * 4];
            float4 xb0 = *(const float4*)&Bs[kk][tx * 4];
            float4 xb1 = *(const float4*)&Bs[kk][64 + tx * 4];
            float a[8] = {xa0.x, xa0.y, xa0.z, xa0.w, xa1.x, xa1.y, xa1.z, xa1.w};
            float b[8] = {xb0.x, xb0.y, xb0.z, xb0.w, xb1.x, xb1.y, xb1.z, xb1.w};
            #pragma unroll
            for (int i = 0; i < 8; i++)
                #pragma unroll
                for (int j = 0; j < 8; j++)
                    acc[i][j] = fmaf(a[i], b[j], acc[i][j]);
        }
    }

    #pragma unroll
    for (int ii = 0; ii < 2; ii++)
      #pragma unroll
      for (int i = 0; i < 4; i++) {
        const long row = m0 + ii * 64 + ty * 4 + i;
        #pragma unroll
        for (int jj = 0; jj < 2; jj++) {
            const long col = n0 + jj * 64 + tx * 4;
            float4 r;
            r.x = acc[ii*4+i][jj*4+0] + bias[col+0];
            r.y = acc[ii*4+i][jj*4+1] + bias[col+1];
            r.z = acc[ii*4+i][jj*4+2] + bias[col+2];
            r.w = acc[ii*4+i][jj*4+3] + bias[col+3];
            if (MODE == 1) {
                float4 rv = *(const float4*)(res + row * (long)N + col);
                r.x += rv.x; r.y += rv.y; r.z += rv.z; r.w += rv.w;
            }
            if (MODE == 2) {
                r.x = fmaxf(r.x, 0.f); r.y = fmaxf(r.y, 0.f);
                r.z = fmaxf(r.z, 0.f); r.w = fmaxf(r.w, 0.f);
            }
            *(float4*)(C + row * (long)N + col) = r;
        }
      }
}

// ---------------------------------------------------------------------------
// QKV projection: per (which, b, h, s-tile) 128x64 tile over K=1024.
// q/k/v[b,h,s,e] = sum_d x[b,s,d] * w[h,d,e] + bias[h,e]
// ---------------------------------------------------------------------------
__global__ __launch_bounds__(256, 2)
void qkv_gemm(const float* __restrict__ x,
              const float* __restrict__ wq, const float* __restrict__ wk,
              const float* __restrict__ wv,
              const float* __restrict__ bq, const float* __restrict__ bk,
              const float* __restrict__ bv)
{
    __shared__ float As[16][132];
    __shared__ float Bs[16][64];

    const int which = blockIdx.z;
    const int bh = blockIdx.y;
    const int b = bh >> 4, h = bh & 15;
    const long s0 = (long)blockIdx.x * 128;

    const float* W  = (which == 0 ? wq : which == 1 ? wk : wv) + (long)h * Dd * DHd;
    const float* Bi = (which == 0 ? bq : which == 1 ? bk : bv) + h * DHd;
    float* Optr = (which == 0 ? g_q : which == 1 ? g_k : g_v)
                  + ((long)bh * Sd + s0) * DHd;
    const float* Ap0 = x + ((long)b * Sd + s0) * Dd;

    const int tid = threadIdx.x;
    const int tx = tid & 15, ty = tid >> 4;
    const int ar = tid >> 2, ac = (tid & 3) << 2;
    const int br = tid >> 4, bc = (tid & 15) << 2;

    float acc[8][4];
    #pragma unroll
    for (int i = 0; i < 8; i++)
        #pragma unroll
        for (int j = 0; j < 4; j++) acc[i][j] = 0.f;

    for (int k0 = 0; k0 < Dd; k0 += 16) {
        float4 a0 = *(const float4*)(Ap0 + (long)ar * Dd + k0 + ac);
        float4 a1 = *(const float4*)(Ap0 + (long)(ar + 64) * Dd + k0 + ac);
        float4 b0 = *(const float4*)(W + (long)(k0 + br) * DHd + bc);
        __syncthreads();
        As[ac+0][ar]    = a0.x; As[ac+1][ar]    = a0.y;
        As[ac+2][ar]    = a0.z; As[ac+3][ar]    = a0.w;
        As[ac+0][ar+64] = a1.x; As[ac+1][ar+64] = a1.y;
        As[ac+2][ar+64] = a1.z; As[ac+3][ar+64] = a1.w;
        *(float4*)&Bs[br][bc] = b0;
        __syncthreads();
        #pragma unroll
        for (int kk = 0; kk < 16; kk++) {
            float4 xa0 = *(const float4*)&As[kk][ty * 4];
            float4 xa1 = *(const float4*)&As[kk][64 + ty * 4];
            float4 vb  = *(const float4*)&Bs[kk][tx * 4];
            float a[8] = {xa0.x, xa0.y, xa0.z, xa0.w, xa1.x, xa1.y, xa1.z, xa1.w};
            #pragma unroll
            for (int i = 0; i < 8; i++) {
                acc[i][0] = fmaf(a[i], vb.x, acc[i][0]);
                acc[i][1] = fmaf(a[i], vb.y, acc[i][1]);
                acc[i][2] = fmaf(a[i], vb.z, acc[i][2]);
                acc[i][3] = fmaf(a[i], vb.w, acc[i][3]);
            }
        }
    }

    const float bb0 = Bi[tx*4+0], bb1 = Bi[tx*4+1], bb2 = Bi[tx*4+2], bb3 = Bi[tx*4+3];
    #pragma unroll
    for (int ii = 0; ii < 2; ii++)
      #pragma unroll
      for (int i = 0; i < 4; i++) {
        const long row = ii * 64 + ty * 4 + i;
        float4 r;
        r.x = acc[ii*4+i][0] + bb0;
        r.y = acc[ii*4+i][1] + bb1;
        r.z = acc[ii*4+i][2] + bb2;
        r.w = acc[ii*4+i][3] + bb3;
        *(float4*)(Optr + row * DHd + tx * 4) = r;
      }
}

// ---------------------------------------------------------------------------
// Flash attention (fp32): one block per (b*H+h, 64-row query tile).
// Online softmax over 32 key tiles of 64. KP buffer holds K^T then P (reused)
// so static smem is exactly 48 KB.
// ---------------------------------------------------------------------------
__global__ __launch_bounds__(256)
void attn_kernel()
{
    __shared__ float Qs[64][64];
    __shared__ float KP[64][64];   // K^T during scores; P during PV
    __shared__ float Vs[64][64];

    const int bh = blockIdx.y;
    const int q0 = blockIdx.x * 64;
    const int b = bh >> 4, h = bh & 15;
    const float* Q = g_q + ((long)bh * Sd + q0) * DHd;
    const float* K = g_k + (long)bh * Sd * DHd;
    const float* V = g_v + (long)bh * Sd * DHd;

    const int tid = threadIdx.x;
    const int tx = tid & 15, ty = tid >> 4;
    const int lr = tid >> 2;            // load row 0..63
    const int lc = (tid & 3) << 2;      // load col chunk

    // Load Q tile, pre-scaled by 1/sqrt(DH)=0.125
    #pragma unroll
    for (int cc = 0; cc < 4; cc++) {
        const int col = lc + cc * 16;
        float4 qv = *(const float4*)(Q + (long)lr * DHd + col);
        float4 qs = make_float4(qv.x * 0.125f, qv.y * 0.125f,
                                qv.z * 0.125f, qv.w * 0.125f);
        *(float4*)&Qs[lr][col] = qs;
    }

    float m_i[4], l_i[4], oacc[4][4];
    #pragma unroll
    for (int i = 0; i < 4; i++) {
        m_i[i] = -CUDART_INF_F; l_i[i] = 0.f;
        #pragma unroll
        for (int j = 0; j < 4; j++) oacc[i][j] = 0.f;
    }

    for (int kt = 0; kt < Sd / 64; kt++) {
        const float* Kt = K + (long)kt * 64 * DHd;
        const float* Vt = V + (long)kt * 64 * DHd;
        __syncthreads();   // prior PV done reading KP/Vs
        #pragma unroll
        for (int cc = 0; cc < 4; cc++) {
            const int col = lc + cc * 16;
            float4 kv = *(const float4*)(Kt + (long)lr * DHd + col);
            KP[col+0][lr] = kv.x; KP[col+1][lr] = kv.y;
            KP[col+2][lr] = kv.z; KP[col+3][lr] = kv.w;
            float4 vv = *(const float4*)(Vt + (long)lr * DHd + col);
            *(float4*)&Vs[lr][col] = vv;
        }
        __syncthreads();

        // scores: s[i][j] = sum_e Qs[row][e] * K^T[e][col]
        float s[4][4];
        #pragma unroll
        for (int i = 0; i < 4; i++)
            #pragma unroll
            for (int j = 0; j < 4; j++) s[i][j] = 0.f;
        #pragma unroll 8
        for (int e = 0; e < 64; e++) {
            float4 kf = *(const float4*)&KP[e][tx * 4];
            float qf0 = Qs[ty*4+0][e], qf1 = Qs[ty*4+1][e];
            float qf2 = Qs[ty*4+2][e], qf3 = Qs[ty*4+3][e];
            s[0][0] = fmaf(qf0, kf.x, s[0][0]); s[0][1] = fmaf(qf0, kf.y, s[0][1]);
            s[0][2] = fmaf(qf0, kf.z, s[0][2]); s[0][3] = fmaf(qf0, kf.w, s[0][3]);
            s[1][0] = fmaf(qf1, kf.x, s[1][0]); s[1][1] = fmaf(qf1, kf.y, s[1][1]);
            s[1][2] = fmaf(qf1, kf.z, s[1][2]); s[1][3] = fmaf(qf1, kf.w, s[1][3]);
            s[2][0] = fmaf(qf2, kf.x, s[2][0]); s[2][1] = fmaf(qf2, kf.y, s[2][1]);
            s[2][2] = fmaf(qf2, kf.z, s[2][2]); s[2][3] = fmaf(qf2, kf.w, s[2][3]);
            s[3][0] = fmaf(qf3, kf.x, s[3][0]); s[3][1] = fmaf(qf3, kf.y, s[3][1]);
            s[3][2] = fmaf(qf3, kf.z, s[3][2]); s[3][3] = fmaf(qf3, kf.w, s[3][3]);
        }

        // online softmax per row (row owned by 16 lanes sharing ty)
        #pragma unroll
        for (int i = 0; i < 4; i++) {
            float mx = fmaxf(fmaxf(s[i][0], s[i][1]), fmaxf(s[i][2], s[i][3]));
            #pragma unroll
            for (int off = 8; off > 0; off >>= 1)
                mx = fmaxf(mx, __shfl_xor_sync(0xffffffffu, mx, off));
            const float mnew = fmaxf(m_i[i], mx);
            const float corr = __expf(m_i[i] - mnew);
            float rsum = 0.f;
            #pragma unroll
            for (int j = 0; j < 4; j++) {
                const float p = __expf(s[i][j] - mnew);
                s[i][j] = p; rsum += p;
            }
            #pragma unroll
            for (int off = 8; off > 0; off >>= 1)
                rsum += __shfl_xor_sync(0xffffffffu, rsum, off);
            l_i[i] = l_i[i] * corr + rsum;
            m_i[i] = mnew;
            #pragma unroll
            for (int j = 0; j < 4; j++) oacc[i][j] *= corr;
        }
        __syncthreads();   // done reading KP as K^T
        #pragma unroll
        for (int i = 0; i < 4; i++)
            *(float4*)&KP[ty*4+i][tx*4] = make_float4(s[i][0], s[i][1], s[i][2], s[i][3]);
        __syncthreads();

        // O += P @ V
        #pragma unroll 8
        for (int kk = 0; kk < 64; kk++) {
            float4 vv = *(const float4*)&Vs[kk][tx * 4];
            #pragma unroll
            for (int i = 0; i < 4; i++) {
                const float p = KP[ty*4+i][kk];
                oacc[i][0] = fmaf(p, vv.x, oacc[i][0]);
                oacc[i][1] = fmaf(p, vv.y, oacc[i][1]);
                oacc[i][2] = fmaf(p, vv.z, oacc[i][2]);
                oacc[i][3] = fmaf(p, vv.w, oacc[i][3]);
            }
        }
    }

    // normalize and store into concat layout [B*S, H*DH]
    #pragma unroll
    for (int i = 0; i < 4; i++) {
        const float inv = 1.f / l_i[i];
        const long row = (long)b * Sd + q0 + ty * 4 + i;
        float4 ov = make_float4(oacc[i][0] * inv, oacc[i][1] * inv,
                                oacc[i][2] * inv, oacc[i][3] * inv);
        *(float4*)(g_o + row * Dd + h * DHd + tx * 4) = ov;
    }
}

// ---------------------------------------------------------------------------
// Row LayerNorm over D=1024: one block (256 threads) per row, 4 floats/thread.
// ---------------------------------------------------------------------------
__global__ __launch_bounds__(256)
void ln_kernel(const float* __restrict__ x, const float* __restrict__ gam,
               const float* __restrict__ bet, float* __restrict__ out)
{
    const long row = blockIdx.x;
    const int t = threadIdx.x;
    float4 v = ((const float4*)(x + row * Dd))[t];
    float s  = v.x + v.y + v.z + v.w;
    float s2 = v.x*v.x + v.y*v.y + v.z*v.z + v.w*v.w;

    __shared__ float sh[16];
    #pragma unroll
    for (int off = 16; off > 0; off >>= 1) {
        s  += __shfl_xor_sync(0xffffffffu, s, off);
        s2 += __shfl_xor_sync(0xffffffffu, s2, off);
    }
    if ((t & 31) == 0) { sh[t >> 5] = s; sh[8 + (t >> 5)] = s2; }
    __syncthreads();
    float ts = 0.f, ts2 = 0.f;
    #pragma unroll
    for (int i = 0; i < 8; i++) { ts += sh[i]; ts2 += sh[8 + i]; }

    const float mu  = ts * (1.f / 1024.f);
    const float var = ts2 * (1.f / 1024.f) - mu * mu;
    const float rs  = rsqrtf(var + 1e-5f);

    float4 g4 = ((const float4*)gam)[t];
    float4 b4 = ((const float4*)bet)[t];
    float4 o;
    o.x = (v.x - mu) * rs * g4.x + b4.x;
    o.y = (v.y - mu) * rs * g4.y + b4.y;
    o.z = (v.z - mu) * rs * g4.z + b4.z;
    o.w = (v.w - mu) * rs * g4.w + b4.w;
    ((float4*)(out + row * Dd))[t] = o;
}

// ---------------------------------------------------------------------------
// Launch
// ---------------------------------------------------------------------------
extern "C" void kernel_launch(void* const* d_in, const int* in_sizes, int n_in,
                              void* d_out, int out_size)
{
    const float* x   = (const float*)d_in[0];
    const float* wq  = (const float*)d_in[1];
    const float* bq  = (const float*)d_in[2];
    const float* wk  = (const float*)d_in[3];
    const float* bk  = (const float*)d_in[4];
    const float* wv  = (const float*)d_in[5];
    const float* bv  = (const float*)d_in[6];
    const float* wo  = (const float*)d_in[7];
    const float* bo  = (const float*)d_in[8];
    const float* g1  = (const float*)d_in[9];
    const float* be1 = (const float*)d_in[10];
    const float* w1  = (const float*)d_in[11];
    const float* b1  = (const float*)d_in[12];
    const float* w2  = (const float*)d_in[13];
    const float* b2  = (const float*)d_in[14];
    const float* g2  = (const float*)d_in[15];
    const float* be2 = (const float*)d_in[16];
    float* out = (float*)d_out;

    float *p_o, *p_r1, *p_y, *p_h, *p_r2;
    cudaGetSymbolAddress((void**)&p_o,  g_o);
    cudaGetSymbolAddress((void**)&p_r1, g_r1);
    cudaGetSymbolAddress((void**)&p_y,  g_y);
    cudaGetSymbolAddress((void**)&p_h,  g_hid);
    cudaGetSymbolAddress((void**)&p_r2, g_r2);

    // 1) QKV projections -> g_q/g_k/g_v [B,H,S,DH]
    qkv_gemm<<<dim3(Sd / 128, Bd * Hn, 3), 256>>>(x, wq, wk, wv, bq, bk, bv);
    // 2) attention -> g_o [B*S, D]
    attn_kernel<<<dim3(Sd / 64, Bd * Hn), 256>>>();
    // 3) O projection + bias + residual(x) -> g_r1
    sgemm128<1><<<dim3(Dd / 128, (Bd * Sd) / 128), 256>>>(
        p_o, Dd, wo, Dd, p_r1, bo, x, Dd, Dd);
    // 4) LN1 -> g_y
    ln_kernel<<<Bd * Sd, 256>>>(p_r1, g1, be1, p_y);
    // 5) FFN1: relu(y @ w1 + b1) -> g_hid
    sgemm128<2><<<dim3(Fd / 128, (Bd * Sd) / 128), 256>>>(
        p_y, Dd, w1, Fd, p_h, b1, nullptr, Fd, Dd);
    // 6) FFN2: h @ w2 + b2 + y -> g_r2
    sgemm128<1><<<dim3(Dd / 128, (Bd * Sd) / 128), 256>>>(
        p_h, Fd, w2, Dd, p_r2, b2, p_y, Dd, Fd);
    // 7) LN2 -> output
    ln_kernel<<<Bd * Sd, 256>>>(p_r2, g2, be2, out);
}

// round 6
// speedup vs baseline: 1.0016x; 1.0016x over previous
#include <cuda_runtime.h>
#include <math_constants.h>

// Problem dimensions (fixed by the reference)
#define Bd  4
#define Sd  2048
#define Dd  1024
#define Hn  16
#define DHd 64
#define Fd  4096

// ---------------------------------------------------------------------------
// Scratch (device globals — allocation-free rule)
// ---------------------------------------------------------------------------
__device__ float g_q  [(size_t)Bd * Hn * Sd * DHd];   // [B,H,S,DH]
__device__ float g_k  [(size_t)Bd * Hn * Sd * DHd];
__device__ float g_v  [(size_t)Bd * Hn * Sd * DHd];
__device__ float g_o  [(size_t)Bd * Sd * Dd];         // attention concat [B*S, D]
__device__ float g_r1 [(size_t)Bd * Sd * Dd];         // x + attn_proj
__device__ float g_y  [(size_t)Bd * Sd * Dd];         // LN1 output
__device__ float g_hid[(size_t)Bd * Sd * Fd];         // FFN hidden [B*S, F]
__device__ float g_r2 [(size_t)Bd * Sd * Dd];         // y + ffn

// ---------------------------------------------------------------------------
// Generic 128x128 SGEMM, BK=16, 256 threads, 8x8 micro-tile.
// C[M,N] = A[M,K](row,lda) @ B[K,N](row,ldb) + bias[N]  (+res / relu per MODE)
// MODE: 0 = bias; 1 = bias + residual; 2 = bias + relu
// ---------------------------------------------------------------------------
template<int MODE>
__global__ __launch_bounds__(256, 2)
void sgemm128(const float* __restrict__ A, int lda,
              const float* __restrict__ B, int ldb,
              float* __restrict__ C,
              const float* __restrict__ bias,
              const float* __restrict__ res,
              int N, int K)
{
    __shared__ float As[16][132];   // transposed A tile, padded (132*4B = 16B-aligned rows)
    __shared__ float Bs[16][128];

    const int tid = threadIdx.x;
    const int tx = tid & 15;
    const int ty = tid >> 4;
    const long m0 = (long)blockIdx.y * 128;
    const long n0 = (long)blockIdx.x * 128;

    const int ar = tid >> 2;          // 0..63
    const int ac = (tid & 3) << 2;    // 0,4,8,12
    const int br = tid >> 4;          // 0..15
    const int bc = (tid & 15) << 2;   // 0..60

    const float* Ap  = A + (m0 + ar)      * (long)lda;
    const float* Ap2 = A + (m0 + ar + 64) * (long)lda;
    const float* Bp  = B + (long)br * ldb + n0;

    float acc[8][8];
    #pragma unroll
    for (int i = 0; i < 8; i++)
        #pragma unroll
        for (int j = 0; j < 8; j++) acc[i][j] = 0.f;

    for (int k0 = 0; k0 < K; k0 += 16) {
        float4 a0 = *(const float4*)(Ap  + k0 + ac);
        float4 a1 = *(const float4*)(Ap2 + k0 + ac);
        float4 b0 = *(const float4*)(Bp + (long)k0 * ldb + bc);
        float4 b1 = *(const float4*)(Bp + (long)k0 * ldb + bc + 64);
        __syncthreads();
        As[ac+0][ar]    = a0.x; As[ac+1][ar]    = a0.y;
        As[ac+2][ar]    = a0.z; As[ac+3][ar]    = a0.w;
        As[ac+0][ar+64] = a1.x; As[ac+1][ar+64] = a1.y;
        As[ac+2][ar+64] = a1.z; As[ac+3][ar+64] = a1.w;
        *(float4*)&Bs[br][bc]      = b0;
        *(float4*)&Bs[br][bc + 64] = b1;
        __syncthreads();
        #pragma unroll
        for (int kk = 0; kk < 16; kk++) {
            float4 xa0 = *(const float4*)&As[kk][ty * 4];
            float4 xa1 = *(const float4*)&As[kk][64 + ty * 4];
            float4 xb0 = *(const float4*)&Bs[kk][tx * 4];
            float4 xb1 = *(const float4*)&Bs[kk][64 + tx * 4];
            float a[8] = {xa0.x, xa0.y, xa0.z, xa0.w, xa1.x, xa1.y, xa1.z, xa1.w};
            float b[8] = {xb0.x, xb0.y, xb0.z, xb0.w, xb1.x, xb1.y, xb1.z, xb1.w};
            #pragma unroll
            for (int i = 0; i < 8; i++)
                #pragma unroll
                for (int j = 0; j < 8; j++)
                    acc[i][j] = fmaf(a[i], b[j], acc[i][j]);
        }
    }

    #pragma unroll
    for (int ii = 0; ii < 2; ii++)
      #pragma unroll
      for (int i = 0; i < 4; i++) {
        const long row = m0 + ii * 64 + ty * 4 + i;
        #pragma unroll
        for (int jj = 0; jj < 2; jj++) {
            const long col = n0 + jj * 64 + tx * 4;
            float4 r;
            r.x = acc[ii*4+i][jj*4+0] + bias[col+0];
            r.y = acc[ii*4+i][jj*4+1] + bias[col+1];
            r.z = acc[ii*4+i][jj*4+2] + bias[col+2];
            r.w = acc[ii*4+i][jj*4+3] + bias[col+3];
            if (MODE == 1) {
                float4 rv = *(const float4*)(res + row * (long)N + col);
                r.x += rv.x; r.y += rv.y; r.z += rv.z; r.w += rv.w;
            }
            if (MODE == 2) {
                r.x = fmaxf(r.x, 0.f); r.y = fmaxf(r.y, 0.f);
                r.z = fmaxf(r.z, 0.f); r.w = fmaxf(r.w, 0.f);
            }
            *(float4*)(C + row * (long)N + col) = r;
        }
      }
}

// ---------------------------------------------------------------------------
// QKV projection: per (which, b, h, s-tile) 128x64 tile over K=1024.
// q/k/v[b,h,s,e] = sum_d x[b,s,d] * w[h,d,e] + bias[h,e]
// ---------------------------------------------------------------------------
__global__ __launch_bounds__(256, 2)
void qkv_gemm(const float* __restrict__ x,
              const float* __restrict__ wq, const float* __restrict__ wk,
              const float* __restrict__ wv,
              const float* __restrict__ bq, const float* __restrict__ bk,
              const float* __restrict__ bv)
{
    __shared__ float As[16][132];
    __shared__ float Bs[16][64];

    const int which = blockIdx.z;
    const int bh = blockIdx.y;
    const int b = bh >> 4, h = bh & 15;
    const long s0 = (long)blockIdx.x * 128;

    const float* W  = (which == 0 ? wq : which == 1 ? wk : wv) + (long)h * Dd * DHd;
    const float* Bi = (which == 0 ? bq : which == 1 ? bk : bv) + h * DHd;
    float* Optr = (which == 0 ? g_q : which == 1 ? g_k : g_v)
                  + ((long)bh * Sd + s0) * DHd;
    const float* Ap0 = x + ((long)b * Sd + s0) * Dd;

    const int tid = threadIdx.x;
    const int tx = tid & 15, ty = tid >> 4;
    const int ar = tid >> 2, ac = (tid & 3) << 2;
    const int br = tid >> 4, bc = (tid & 15) << 2;

    float acc[8][4];
    #pragma unroll
    for (int i = 0; i < 8; i++)
        #pragma unroll
        for (int j = 0; j < 4; j++) acc[i][j] = 0.f;

    for (int k0 = 0; k0 < Dd; k0 += 16) {
        float4 a0 = *(const float4*)(Ap0 + (long)ar * Dd + k0 + ac);
        float4 a1 = *(const float4*)(Ap0 + (long)(ar + 64) * Dd + k0 + ac);
        float4 b0 = *(const float4*)(W + (long)(k0 + br) * DHd + bc);
        __syncthreads();
        As[ac+0][ar]    = a0.x; As[ac+1][ar]    = a0.y;
        As[ac+2][ar]    = a0.z; As[ac+3][ar]    = a0.w;
        As[ac+0][ar+64] = a1.x; As[ac+1][ar+64] = a1.y;
        As[ac+2][ar+64] = a1.z; As[ac+3][ar+64] = a1.w;
        *(float4*)&Bs[br][bc] = b0;
        __syncthreads();
        #pragma unroll
        for (int kk = 0; kk < 16; kk++) {
            float4 xa0 = *(const float4*)&As[kk][ty * 4];
            float4 xa1 = *(const float4*)&As[kk][64 + ty * 4];
            float4 vb  = *(const float4*)&Bs[kk][tx * 4];
            float a[8] = {xa0.x, xa0.y, xa0.z, xa0.w, xa1.x, xa1.y, xa1.z, xa1.w};
            #pragma unroll
            for (int i = 0; i < 8; i++) {
                acc[i][0] = fmaf(a[i], vb.x, acc[i][0]);
                acc[i][1] = fmaf(a[i], vb.y, acc[i][1]);
                acc[i][2] = fmaf(a[i], vb.z, acc[i][2]);
                acc[i][3] = fmaf(a[i], vb.w, acc[i][3]);
            }
        }
    }

    const float bb0 = Bi[tx*4+0], bb1 = Bi[tx*4+1], bb2 = Bi[tx*4+2], bb3 = Bi[tx*4+3];
    #pragma unroll
    for (int ii = 0; ii < 2; ii++)
      #pragma unroll
      for (int i = 0; i < 4; i++) {
        const long row = ii * 64 + ty * 4 + i;
        float4 r;
        r.x = acc[ii*4+i][0] + bb0;
        r.y = acc[ii*4+i][1] + bb1;
        r.z = acc[ii*4+i][2] + bb2;
        r.w = acc[ii*4+i][3] + bb3;
        *(float4*)(Optr + row * DHd + tx * 4) = r;
      }
}

// ---------------------------------------------------------------------------
// Flash attention (fp32): one block per (b*H+h, 64-row query tile).
// Online softmax over 32 key tiles of 64. KP buffer holds K^T then P (reused)
// so static smem is exactly 48 KB.
// ---------------------------------------------------------------------------
__global__ __launch_bounds__(256)
void attn_kernel()
{
    __shared__ float Qs[64][64];
    __shared__ float KP[64][64];   // K^T during scores; P during PV
    __shared__ float Vs[64][64];

    const int bh = blockIdx.y;
    const int q0 = blockIdx.x * 64;
    const int b = bh >> 4, h = bh & 15;
    const float* Q = g_q + ((long)bh * Sd + q0) * DHd;
    const float* K = g_k + (long)bh * Sd * DHd;
    const float* V = g_v + (long)bh * Sd * DHd;

    const int tid = threadIdx.x;
    const int tx = tid & 15, ty = tid >> 4;
    const int lr = tid >> 2;            // load row 0..63
    const int lc = (tid & 3) << 2;      // load col chunk

    // Load Q tile, pre-scaled by 1/sqrt(DH)=0.125
    #pragma unroll
    for (int cc = 0; cc < 4; cc++) {
        const int col = lc + cc * 16;
        float4 qv = *(const float4*)(Q + (long)lr * DHd + col);
        float4 qs = make_float4(qv.x * 0.125f, qv.y * 0.125f,
                                qv.z * 0.125f, qv.w * 0.125f);
        *(float4*)&Qs[lr][col] = qs;
    }

    float m_i[4], l_i[4], oacc[4][4];
    #pragma unroll
    for (int i = 0; i < 4; i++) {
        m_i[i] = -CUDART_INF_F; l_i[i] = 0.f;
        #pragma unroll
        for (int j = 0; j < 4; j++) oacc[i][j] = 0.f;
    }

    for (int kt = 0; kt < Sd / 64; kt++) {
        const float* Kt = K + (long)kt * 64 * DHd;
        const float* Vt = V + (long)kt * 64 * DHd;
        __syncthreads();   // prior PV done reading KP/Vs
        #pragma unroll
        for (int cc = 0; cc < 4; cc++) {
            const int col = lc + cc * 16;
            float4 kv = *(const float4*)(Kt + (long)lr * DHd + col);
            KP[col+0][lr] = kv.x; KP[col+1][lr] = kv.y;
            KP[col+2][lr] = kv.z; KP[col+3][lr] = kv.w;
            float4 vv = *(const float4*)(Vt + (long)lr * DHd + col);
            *(float4*)&Vs[lr][col] = vv;
        }
        __syncthreads();

        // scores: s[i][j] = sum_e Qs[row][e] * K^T[e][col]
        float s[4][4];
        #pragma unroll
        for (int i = 0; i < 4; i++)
            #pragma unroll
            for (int j = 0; j < 4; j++) s[i][j] = 0.f;
        #pragma unroll 8
        for (int e = 0; e < 64; e++) {
            float4 kf = *(const float4*)&KP[e][tx * 4];
            float qf0 = Qs[ty*4+0][e], qf1 = Qs[ty*4+1][e];
            float qf2 = Qs[ty*4+2][e], qf3 = Qs[ty*4+3][e];
            s[0][0] = fmaf(qf0, kf.x, s[0][0]); s[0][1] = fmaf(qf0, kf.y, s[0][1]);
            s[0][2] = fmaf(qf0, kf.z, s[0][2]); s[0][3] = fmaf(qf0, kf.w, s[0][3]);
            s[1][0] = fmaf(qf1, kf.x, s[1][0]); s[1][1] = fmaf(qf1, kf.y, s[1][1]);
            s[1][2] = fmaf(qf1, kf.z, s[1][2]); s[1][3] = fmaf(qf1, kf.w, s[1][3]);
            s[2][0] = fmaf(qf2, kf.x, s[2][0]); s[2][1] = fmaf(qf2, kf.y, s[2][1]);
            s[2][2] = fmaf(qf2, kf.z, s[2][2]); s[2][3] = fmaf(qf2, kf.w, s[2][3]);
            s[3][0] = fmaf(qf3, kf.x, s[3][0]); s[3][1] = fmaf(qf3, kf.y, s[3][1]);
            s[3][2] = fmaf(qf3, kf.z, s[3][2]); s[3][3] = fmaf(qf3, kf.w, s[3][3]);
        }

        // online softmax per row (row owned by 16 lanes sharing ty)
        #pragma unroll
        for (int i = 0; i < 4; i++) {
            float mx = fmaxf(fmaxf(s[i][0], s[i][1]), fmaxf(s[i][2], s[i][3]));
            #pragma unroll
            for (int off = 8; off > 0; off >>= 1)
                mx = fmaxf(mx, __shfl_xor_sync(0xffffffffu, mx, off));
            const float mnew = fmaxf(m_i[i], mx);
            const float corr = __expf(m_i[i] - mnew);
            float rsum = 0.f;
            #pragma unroll
            for (int j = 0; j < 4; j++) {
                const float p = __expf(s[i][j] - mnew);
                s[i][j] = p; rsum += p;
            }
            #pragma unroll
            for (int off = 8; off > 0; off >>= 1)
                rsum += __shfl_xor_sync(0xffffffffu, rsum, off);
            l_i[i] = l_i[i] * corr + rsum;
            m_i[i] = mnew;
            #pragma unroll
            for (int j = 0; j < 4; j++) oacc[i][j] *= corr;
        }
        __syncthreads();   // done reading KP as K^T
        #pragma unroll
        for (int i = 0; i < 4; i++)
            *(float4*)&KP[ty*4+i][tx*4] = make_float4(s[i][0], s[i][1], s[i][2], s[i][3]);
        __syncthreads();

        // O += P @ V
        #pragma unroll 8
        for (int kk = 0; kk < 64; kk++) {
            float4 vv = *(const float4*)&Vs[kk][tx * 4];
            #pragma unroll
            for (int i = 0; i < 4; i++) {
                const float p = KP[ty*4+i][kk];
                oacc[i][0] = fmaf(p, vv.x, oacc[i][0]);
                oacc[i][1] = fmaf(p, vv.y, oacc[i][1]);
                oacc[i][2] = fmaf(p, vv.z, oacc[i][2]);
                oacc[i][3] = fmaf(p, vv.w, oacc[i][3]);
            }
        }
    }

    // normalize and store into concat layout [B*S, H*DH]
    #pragma unroll
    for (int i = 0; i < 4; i++) {
        const float inv = 1.f / l_i[i];
        const long row = (long)b * Sd + q0 + ty * 4 + i;
        float4 ov = make_float4(oacc[i][0] * inv, oacc[i][1] * inv,
                                oacc[i][2] * inv, oacc[i][3] * inv);
        *(float4*)(g_o + row * Dd + h * DHd + tx * 4) = ov;
    }
}

// ---------------------------------------------------------------------------
// Row LayerNorm over D=1024: one block (256 threads) per row, 4 floats/thread.
// ---------------------------------------------------------------------------
__global__ __launch_bounds__(256)
void ln_kernel(const float* __restrict__ x, const float* __restrict__ gam,
               const float* __restrict__ bet, float* __restrict__ out)
{
    const long row = blockIdx.x;
    const int t = threadIdx.x;
    float4 v = ((const float4*)(x + row * Dd))[t];
    float s  = v.x + v.y + v.z + v.w;
    float s2 = v.x*v.x + v.y*v.y + v.z*v.z + v.w*v.w;

    __shared__ float sh[16];
    #pragma unroll
    for (int off = 16; off > 0; off >>= 1) {
        s  += __shfl_xor_sync(0xffffffffu, s, off);
        s2 += __shfl_xor_sync(0xffffffffu, s2, off);
    }
    if ((t & 31) == 0) { sh[t >> 5] = s; sh[8 + (t >> 5)] = s2; }
    __syncthreads();
    float ts = 0.f, ts2 = 0.f;
    #pragma unroll
    for (int i = 0; i < 8; i++) { ts += sh[i]; ts2 += sh[8 + i]; }

    const float mu  = ts * (1.f / 1024.f);
    const float var = ts2 * (1.f / 1024.f) - mu * mu;
    const float rs  = rsqrtf(var + 1e-5f);

    float4 g4 = ((const float4*)gam)[t];
    float4 b4 = ((const float4*)bet)[t];
    float4 o;
    o.x = (v.x - mu) * rs * g4.x + b4.x;
    o.y = (v.y - mu) * rs * g4.y + b4.y;
    o.z = (v.z - mu) * rs * g4.z + b4.z;
    o.w = (v.w - mu) * rs * g4.w + b4.w;
    ((float4*)(out + row * Dd))[t] = o;
}

// ---------------------------------------------------------------------------
// Launch
// ---------------------------------------------------------------------------
extern "C" void kernel_launch(void* const* d_in, const int* in_sizes, int n_in,
                              void* d_out, int out_size)
{
    const float* x   = (const float*)d_in[0];
    const float* wq  = (const float*)d_in[1];
    const float* bq  = (const float*)d_in[2];
    const float* wk  = (const float*)d_in[3];
    const float* bk  = (const float*)d_in[4];
    const float* wv  = (const float*)d_in[5];
    const float* bv  = (const float*)d_in[6];
    const float* wo  = (const float*)d_in[7];
    const float* bo  = (const float*)d_in[8];
    const float* g1  = (const float*)d_in[9];
    const float* be1 = (const float*)d_in[10];
    const float* w1  = (const float*)d_in[11];
    const float* b1  = (const float*)d_in[12];
    const float* w2  = (const float*)d_in[13];
    const float* b2  = (const float*)d_in[14];
    const float* g2  = (const float*)d_in[15];
    const float* be2 = (const float*)d_in[16];
    float* out = (float*)d_out;

    float *p_o, *p_r1, *p_y, *p_h, *p_r2;
    cudaGetSymbolAddress((void**)&p_o,  g_o);
    cudaGetSymbolAddress((void**)&p_r1, g_r1);
    cudaGetSymbolAddress((void**)&p_y,  g_y);
    cudaGetSymbolAddress((void**)&p_h,  g_hid);
    cudaGetSymbolAddress((void**)&p_r2, g_r2);

    // 1) QKV projections -> g_q/g_k/g_v [B,H,S,DH]
    qkv_gemm<<<dim3(Sd / 128, Bd * Hn, 3), 256>>>(x, wq, wk, wv, bq, bk, bv);
    // 2) attention -> g_o [B*S, D]
    attn_kernel<<<dim3(Sd / 64, Bd * Hn), 256>>>();
    // 3) O projection + bias + residual(x) -> g_r1
    sgemm128<1><<<dim3(Dd / 128, (Bd * Sd) / 128), 256>>>(
        p_o, Dd, wo, Dd, p_r1, bo, x, Dd, Dd);
    // 4) LN1 -> g_y
    ln_kernel<<<Bd * Sd, 256>>>(p_r1, g1, be1, p_y);
    // 5) FFN1: relu(y @ w1 + b1) -> g_hid
    sgemm128<2><<<dim3(Fd / 128, (Bd * Sd) / 128), 256>>>(
        p_y, Dd, w1, Fd, p_h, b1, nullptr, Fd, Dd);
    // 6) FFN2: h @ w2 + b2 + y -> g_r2
    sgemm128<1><<<dim3(Dd / 128, (Bd * Sd) / 128), 256>>>(
        p_h, Fd, w2, Dd, p_r2, b2, p_y, Dd, Fd);
    // 7) LN2 -> output
    ln_kernel<<<Bd * Sd, 256>>>(p_r2, g2, be2, out);
}